// round 9
// baseline (speedup 1.0000x reference)
#include <cuda_runtime.h>
#include <stdint.h>

#define NPTS    262144
#define NWTILES 8192          // warp-tiles of 32 points
#define TMASK   0x7FFFFu
#define RS      72            // staging row stride (floats)
#define THREADS 512
#define NWARP   16
#define NCTA    148

// weight fragment arrays (uint4 units)
#define WF_L1 0               // Kt2 Nt8 -> 512
#define WF_L2 512             // Kt4 Nt2 -> 256
#define WF_C1 768             // Kt2 Nt8 -> 512
#define WF_C2 1280            // Kt4 Nt8 -> 1024
#define WF_C3 2304            // Kt4 Nt8 -> 1024
#define WF_C4 3328            // Kt4 Nt1 -> 128
#define WF_TOT 3456
#define BIAS_F (WF_TOT * 4)   // float idx 13824; db1(64) db2(16) cb1(64) cb2(64) cb3(64) cb4(8)
#define STG_F  (BIAS_F + 280) // 14104, 16B aligned
#define SMEM_FLOATS (STG_F + NWARP * 32 * RS)
#define SMEM_BYTES  (SMEM_FLOATS * 4)

typedef unsigned long long u64;

__device__ __forceinline__ uint32_t pkb(float lo, float hi) {
    uint32_t r; asm("cvt.rn.bf16x2.f32 %0, %1, %2;" : "=r"(r) : "f"(hi), "f"(lo)); return r;
}
__device__ __forceinline__ float lof(uint32_t u) { return __uint_as_float(u << 16); }
__device__ __forceinline__ float hif(uint32_t u) { return __uint_as_float(u & 0xffff0000u); }

__device__ __forceinline__ void mma16(float* d, const uint32_t* a, uint32_t b0, uint32_t b1) {
    asm volatile(
        "mma.sync.aligned.m16n8k16.row.col.f32.bf16.bf16.f32 "
        "{%0,%1,%2,%3},{%4,%5,%6,%7},{%8,%9},{%0,%1,%2,%3};"
        : "+f"(d[0]), "+f"(d[1]), "+f"(d[2]), "+f"(d[3])
        : "r"(a[0]), "r"(a[1]), "r"(a[2]), "r"(a[3]), "r"(b0), "r"(b1));
}

// acc[Nt][4] = A(16xK fp32 staging) @ W(KxN), 3-pass bf16 (AhBh + AlBh + AhBl)
template<int K, int N>
__device__ __forceinline__ void mma_compute(const uint4* __restrict__ Wf,
                                            const float* __restrict__ Aw,
                                            int m, int lane, float acc[N / 8][4])
{
    constexpr int Kt = K / 16, Nt = N / 8;
    const int g = lane >> 2, tig = lane & 3;
#pragma unroll
    for (int nt = 0; nt < Nt; nt++)
        acc[nt][0] = acc[nt][1] = acc[nt][2] = acc[nt][3] = 0.f;
    const float* base = Aw + (16 * m + g) * RS + 2 * tig;
#pragma unroll
    for (int kt = 0; kt < Kt; kt++) {
        const float* ar = base + kt * 16;
        float2 va = *(const float2*)(ar);
        float2 vc = *(const float2*)(ar + 8 * RS);
        float2 vb = *(const float2*)(ar + 8);
        float2 vd = *(const float2*)(ar + 8 * RS + 8);
        uint32_t ah[4], al[4];
        ah[0] = pkb(va.x, va.y); al[0] = pkb(va.x - lof(ah[0]), va.y - hif(ah[0]));
        ah[1] = pkb(vc.x, vc.y); al[1] = pkb(vc.x - lof(ah[1]), vc.y - hif(ah[1]));
        ah[2] = pkb(vb.x, vb.y); al[2] = pkb(vb.x - lof(ah[2]), vb.y - hif(ah[2]));
        ah[3] = pkb(vd.x, vd.y); al[3] = pkb(vd.x - lof(ah[3]), vd.y - hif(ah[3]));
#pragma unroll
        for (int nt = 0; nt < Nt; nt++) {
            uint4 B = Wf[(nt * Kt + kt) * 32 + lane];
            mma16(acc[nt], ah, B.x, B.y);
            mma16(acc[nt], al, B.x, B.y);
            mma16(acc[nt], ah, B.z, B.w);
        }
    }
}

template<int K, int N>
__device__ __forceinline__ void layer_relu(const uint4* __restrict__ Wf,
                                           const float* __restrict__ bias,
                                           float* __restrict__ Aw, int lane)
{
    constexpr int Nt = N / 8;
    const int g = lane >> 2, tig = lane & 3;
#pragma unroll
    for (int m = 0; m < 2; m++) {
        float acc[Nt][4];
        mma_compute<K, N>(Wf, Aw, m, lane, acc);
        __syncwarp();
        float* s0 = Aw + (16 * m + g) * RS + 2 * tig;
#pragma unroll
        for (int nt = 0; nt < Nt; nt++) {
            float b0 = bias[nt * 8 + 2 * tig], b1 = bias[nt * 8 + 2 * tig + 1];
            *(float2*)(s0 + nt * 8) =
                make_float2(fmaxf(acc[nt][0] + b0, 0.f), fmaxf(acc[nt][1] + b1, 0.f));
            *(float2*)(s0 + 8 * RS + nt * 8) =
                make_float2(fmaxf(acc[nt][2] + b0, 0.f), fmaxf(acc[nt][3] + b1, 0.f));
        }
        __syncwarp();
    }
}

// density layer 2: 64 -> 16, no relu, writes cols 16..31
__device__ __forceinline__ void layer_l2(const uint4* __restrict__ Wf,
                                         const float* __restrict__ bias,
                                         float* __restrict__ Aw, int lane)
{
    const int g = lane >> 2, tig = lane & 3;
#pragma unroll
    for (int m = 0; m < 2; m++) {
        float acc[2][4];
        mma_compute<64, 16>(Wf, Aw, m, lane, acc);
        __syncwarp();
        float* s0 = Aw + (16 * m + g) * RS + 16 + 2 * tig;
#pragma unroll
        for (int nt = 0; nt < 2; nt++) {
            float b0 = bias[nt * 8 + 2 * tig], b1 = bias[nt * 8 + 2 * tig + 1];
            *(float2*)(s0 + nt * 8) = make_float2(acc[nt][0] + b0, acc[nt][1] + b1);
            *(float2*)(s0 + 8 * RS + nt * 8) = make_float2(acc[nt][2] + b0, acc[nt][3] + b1);
        }
        __syncwarp();
    }
}

__device__ __forceinline__ float sigm(float v) { return 1.f / (1.f + expf(-v)); }

__device__ __forceinline__ void layer_c4(const uint4* __restrict__ Wf,
                                         const float* __restrict__ bias,
                                         const float* __restrict__ Aw, int lane,
                                         float* __restrict__ out, int pbase)
{
    const int g = lane >> 2, tig = lane & 3;
#pragma unroll
    for (int m = 0; m < 2; m++) {
        float acc[1][4];
        mma_compute<64, 8>(Wf, Aw, m, lane, acc);
        int r0 = pbase + 16 * m + g;
        int c = 2 * tig;
        if (c < 3) {
            float b = bias[c];
            out[NPTS + 3 * r0 + c]       = sigm(acc[0][0] + b);
            out[NPTS + 3 * (r0 + 8) + c] = sigm(acc[0][2] + b);
        }
        if (c + 1 < 3) {
            float b = bias[c + 1];
            out[NPTS + 3 * r0 + c + 1]       = sigm(acc[0][1] + b);
            out[NPTS + 3 * (r0 + 8) + c + 1] = sigm(acc[0][3] + b);
        }
    }
    __syncwarp();
}

__device__ __forceinline__ void stage_w(uint4* __restrict__ dst, const float* __restrict__ w,
                                        int Kt, int Nt, int rN, int tid)
{
    int tot = Kt * Nt * 32;
    for (int idx = tid; idx < tot; idx += THREADS) {
        int lane = idx & 31, f = idx >> 5;
        int kt = f % Kt, nt = f / Kt;
        int g = lane >> 2, tig = lane & 3;
        int n = nt * 8 + g;
        int k0 = kt * 16 + 2 * tig;
        float w00 = 0.f, w01 = 0.f, w10 = 0.f, w11 = 0.f;
        if (n < rN) {
            w00 = w[k0 * rN + n];       w01 = w[(k0 + 1) * rN + n];
            w10 = w[(k0 + 8) * rN + n]; w11 = w[(k0 + 9) * rN + n];
        }
        uint32_t h0 = pkb(w00, w01), h1 = pkb(w10, w11);
        uint32_t l0 = pkb(w00 - lof(h0), w01 - hif(h0));
        uint32_t l1 = pkb(w10 - lof(h1), w11 - hif(h1));
        dst[idx] = make_uint4(h0, h1, l0, l1);
    }
}

__global__ void __launch_bounds__(THREADS, 1)
nerf_mma_kernel(const float* __restrict__ coords,
                const float* __restrict__ dirs,
                const u64*   __restrict__ emb,
                const float* __restrict__ dw1, const float* __restrict__ db1,
                const float* __restrict__ dw2, const float* __restrict__ db2,
                const float* __restrict__ cw1, const float* __restrict__ cb1,
                const float* __restrict__ cw2, const float* __restrict__ cb2,
                const float* __restrict__ cw3, const float* __restrict__ cb3,
                const float* __restrict__ cw4, const float* __restrict__ cb4,
                float* __restrict__ out)
{
    extern __shared__ float sm[];
    uint4* wf = (uint4*)sm;
    const int tid = threadIdx.x;

    stage_w(wf + WF_L1, dw1, 2, 8, 64, tid);
    stage_w(wf + WF_L2, dw2, 4, 2, 16, tid);
    stage_w(wf + WF_C1, cw1, 2, 8, 64, tid);
    stage_w(wf + WF_C2, cw2, 4, 8, 64, tid);
    stage_w(wf + WF_C3, cw3, 4, 8, 64, tid);
    stage_w(wf + WF_C4, cw4, 4, 1,  3, tid);
    for (int i = tid; i < 64; i += THREADS) sm[BIAS_F + i] = db1[i];
    for (int i = tid; i < 16; i += THREADS) sm[BIAS_F + 64 + i] = db2[i];
    for (int i = tid; i < 64; i += THREADS) sm[BIAS_F + 80 + i] = cb1[i];
    for (int i = tid; i < 64; i += THREADS) sm[BIAS_F + 144 + i] = cb2[i];
    for (int i = tid; i < 64; i += THREADS) sm[BIAS_F + 208 + i] = cb3[i];
    for (int i = tid; i < 8;  i += THREADS) sm[BIAS_F + 272 + i] = (i < 3) ? cb4[i] : 0.f;
    __syncthreads();

    const int lane = tid & 31, warp = tid >> 5;
    float* Aw = sm + STG_F + warp * (32 * RS);
    float* frow = Aw + lane * RS;

    const float RESV[16] = {16.f, 20.f, 25.f, 32.f, 40.f, 50.f, 64.f, 80.f,
                            101.f, 128.f, 161.f, 203.f, 256.f, 322.f, 406.f, 512.f};

    for (int wt = blockIdx.x * NWARP + warp; wt < NWTILES; wt += NCTA * NWARP) {
        const int p = wt * 32 + lane;

        // ---------- hash-grid encode: write each level's float2 straight to smem ----
        const float cx = coords[3 * p + 0];
        const float cy = coords[3 * p + 1];
        const float cz = coords[3 * p + 2];

#pragma unroll
        for (int l = 0; l < 16; l++) {
            const float r = RESV[l];
            float fx = cx * r, fy = cy * r, fz = cz * r;
            float xf = floorf(fx), yf = floorf(fy), zf = floorf(fz);
            float tx = fx - xf, ty = fy - yf, tz = fz - zf;
            uint32_t px = (uint32_t)xf, py = (uint32_t)yf, pz = (uint32_t)zf;
            uint32_t hx0 = px,                hx1 = px + 1u;
            uint32_t hy0 = py * 2654435761u,  hy1 = hy0 + 2654435761u;
            uint32_t hz0 = pz * 805459861u,   hz1 = hz0 + 805459861u;
            const u64* tt = emb + ((size_t)l << 19);
            u64 e000 = __ldg(tt + ((hx0 ^ hy0 ^ hz0) & TMASK));
            u64 e001 = __ldg(tt + ((hx0 ^ hy0 ^ hz1) & TMASK));
            u64 e010 = __ldg(tt + ((hx0 ^ hy1 ^ hz0) & TMASK));
            u64 e011 = __ldg(tt + ((hx0 ^ hy1 ^ hz1) & TMASK));
            u64 e100 = __ldg(tt + ((hx1 ^ hy0 ^ hz0) & TMASK));
            u64 e101 = __ldg(tt + ((hx1 ^ hy0 ^ hz1) & TMASK));
            u64 e110 = __ldg(tt + ((hx1 ^ hy1 ^ hz0) & TMASK));
            u64 e111 = __ldg(tt + ((hx1 ^ hy1 ^ hz1) & TMASK));

            float ux = 1.f - tx, uy = 1.f - ty, uz = 1.f - tz;
            float w00 = ux * uy, w01 = ux * ty, w10 = tx * uy, w11 = tx * ty;
            float2 v; float a0 = 0.f, a1 = 0.f, w;
            w = w00 * uz; v = *(float2*)&e000; a0 = fmaf(w, v.x, a0); a1 = fmaf(w, v.y, a1);
            w = w00 * tz; v = *(float2*)&e001; a0 = fmaf(w, v.x, a0); a1 = fmaf(w, v.y, a1);
            w = w01 * uz; v = *(float2*)&e010; a0 = fmaf(w, v.x, a0); a1 = fmaf(w, v.y, a1);
            w = w01 * tz; v = *(float2*)&e011; a0 = fmaf(w, v.x, a0); a1 = fmaf(w, v.y, a1);
            w = w10 * uz; v = *(float2*)&e100; a0 = fmaf(w, v.x, a0); a1 = fmaf(w, v.y, a1);
            w = w10 * tz; v = *(float2*)&e101; a0 = fmaf(w, v.x, a0); a1 = fmaf(w, v.y, a1);
            w = w11 * uz; v = *(float2*)&e110; a0 = fmaf(w, v.x, a0); a1 = fmaf(w, v.y, a1);
            w = w11 * tz; v = *(float2*)&e111; a0 = fmaf(w, v.x, a0); a1 = fmaf(w, v.y, a1);
            *(float2*)(frow + 2 * l) = make_float2(a0, a1);
        }
        __syncwarp();

        // ---------- density MLP ----------
        layer_relu<32, 64>(wf + WF_L1, sm + BIAS_F, Aw, lane);
        layer_l2(wf + WF_L2, sm + BIAS_F + 64, Aw, lane);

        out[p] = expf(frow[16]);

        // ---------- SH deg-4 into cols 0..15 (dirs reloaded here) ----------
        {
            float dxr = dirs[3 * p + 0];
            float dyr = dirs[3 * p + 1];
            float dzr = dirs[3 * p + 2];
            float nrm = sqrtf(dxr * dxr + dyr * dyr + dzr * dzr);
            float x = dxr / nrm, y = dyr / nrm, z = dzr / nrm;
            x = ((x + 1.f) * 0.5f) * 2.f - 1.f;
            y = ((y + 1.f) * 0.5f) * 2.f - 1.f;
            z = ((z + 1.f) * 0.5f) * 2.f - 1.f;
            float xx = x * x, yy = y * y, zz = z * z;
            float xy = x * y, yz = y * z, xz = x * z;
            *(float4*)(frow + 0) = make_float4(
                0.28209479177387814f,
                -0.48860251190291987f * y,
                 0.48860251190291987f * z,
                -0.48860251190291987f * x);
            *(float4*)(frow + 4) = make_float4(
                 1.0925484305920792f * xy,
                -1.0925484305920792f * yz,
                 0.94617469575756f * zz - 0.31539156525252f,
                -1.0925484305920792f * xz);
            *(float4*)(frow + 8) = make_float4(
                 0.5462742152960396f * (xx - yy),
                 0.5900435899266435f * y * (-3.0f * xx + yy),
                 2.890611442640554f * xy * z,
                 0.4570457994644657f * y * (1.0f - 5.0f * zz));
            *(float4*)(frow + 12) = make_float4(
                 0.3731763325901154f * z * (5.0f * zz - 3.0f),
                 0.4570457994644657f * x * (1.0f - 5.0f * zz),
                 1.445305721320277f * z * (xx - yy),
                 0.5900435899266435f * x * (xx - 3.0f * yy));
        }
        __syncwarp();

        // ---------- color MLP ----------
        layer_relu<32, 64>(wf + WF_C1, sm + BIAS_F + 80,  Aw, lane);
        layer_relu<64, 64>(wf + WF_C2, sm + BIAS_F + 144, Aw, lane);
        layer_relu<64, 64>(wf + WF_C3, sm + BIAS_F + 208, Aw, lane);
        layer_c4(wf + WF_C4, sm + BIAS_F + 272, Aw, lane, out, wt * 32);
    }
}

extern "C" void kernel_launch(void* const* d_in, const int* in_sizes, int n_in,
                              void* d_out, int out_size)
{
    const float* coords = (const float*)d_in[0];
    const float* dirs   = (const float*)d_in[1];
    const u64*   emb    = (const u64*)d_in[2];
    const float* dw1 = (const float*)d_in[3];
    const float* db1 = (const float*)d_in[4];
    const float* dw2 = (const float*)d_in[5];
    const float* db2 = (const float*)d_in[6];
    const float* cw1 = (const float*)d_in[7];
    const float* cb1 = (const float*)d_in[8];
    const float* cw2 = (const float*)d_in[9];
    const float* cb2 = (const float*)d_in[10];
    const float* cw3 = (const float*)d_in[11];
    const float* cb3 = (const float*)d_in[12];
    const float* cw4 = (const float*)d_in[13];
    const float* cb4 = (const float*)d_in[14];
    float* out = (float*)d_out;

    cudaFuncSetAttribute(nerf_mma_kernel,
                         cudaFuncAttributeMaxDynamicSharedMemorySize, SMEM_BYTES);

    nerf_mma_kernel<<<NCTA, THREADS, SMEM_BYTES>>>(
        coords, dirs, emb,
        dw1, db1, dw2, db2,
        cw1, cb1, cw2, cb2, cw3, cb3, cw4, cb4,
        out);
}

// round 10
// speedup vs baseline: 1.2655x; 1.2655x over previous
#include <cuda_runtime.h>
#include <stdint.h>

#define NPTS    262144
#define NT64    4096          // 64-point warp-tiles
#define TMASK   0x7FFFFu
#define RS      72            // staging row stride (floats)
#define THREADS 288
#define NWARP   9
#define NCTA    148

// weight fragment arrays (uint4 units)
#define WF_L1 0               // Kt2 Nt8 -> 512
#define WF_L2 512             // Kt4 Nt2 -> 256
#define WF_C1 768             // Kt2 Nt8 -> 512
#define WF_C2 1280            // Kt4 Nt8 -> 1024
#define WF_C3 2304            // Kt4 Nt8 -> 1024
#define WF_C4 3328            // Kt4 Nt1 -> 128
#define WF_TOT 3456
#define BIAS_F (WF_TOT * 4)   // float idx 13824
#define STG_F  (BIAS_F + 280) // 14104, 16B aligned
#define SMEM_FLOATS (STG_F + NWARP * 64 * RS)
#define SMEM_BYTES  (SMEM_FLOATS * 4)

typedef unsigned long long u64;

__constant__ float RESV[16] = {16.f, 20.f, 25.f, 32.f, 40.f, 50.f, 64.f, 80.f,
                               101.f, 128.f, 161.f, 203.f, 256.f, 322.f, 406.f, 512.f};

__device__ unsigned int g_tile_ctr;

__global__ void zero_ctr_kernel() { g_tile_ctr = 0u; }

__device__ __forceinline__ uint32_t pkb(float lo, float hi) {
    uint32_t r; asm("cvt.rn.bf16x2.f32 %0, %1, %2;" : "=r"(r) : "f"(hi), "f"(lo)); return r;
}
__device__ __forceinline__ float lof(uint32_t u) { return __uint_as_float(u << 16); }
__device__ __forceinline__ float hif(uint32_t u) { return __uint_as_float(u & 0xffff0000u); }

__device__ __forceinline__ void mma16(float* d, const uint32_t* a, uint32_t b0, uint32_t b1) {
    asm volatile(
        "mma.sync.aligned.m16n8k16.row.col.f32.bf16.bf16.f32 "
        "{%0,%1,%2,%3},{%4,%5,%6,%7},{%8,%9},{%0,%1,%2,%3};"
        : "+f"(d[0]), "+f"(d[1]), "+f"(d[2]), "+f"(d[3])
        : "r"(a[0]), "r"(a[1]), "r"(a[2]), "r"(a[3]), "r"(b0), "r"(b1));
}

// acc[Nt][4] = A(16xK fp32 staging, m-tile m) @ W(KxN), 3-pass bf16
template<int K, int N>
__device__ __forceinline__ void mma_compute(const uint4* __restrict__ Wf,
                                            const float* __restrict__ Aw,
                                            int m, int lane, float acc[N / 8][4])
{
    constexpr int Kt = K / 16, Nt = N / 8;
    const int g = lane >> 2, tig = lane & 3;
#pragma unroll
    for (int nt = 0; nt < Nt; nt++)
        acc[nt][0] = acc[nt][1] = acc[nt][2] = acc[nt][3] = 0.f;
    const float* base = Aw + (16 * m + g) * RS + 2 * tig;
#pragma unroll
    for (int kt = 0; kt < Kt; kt++) {
        const float* ar = base + kt * 16;
        float2 va = *(const float2*)(ar);
        float2 vc = *(const float2*)(ar + 8 * RS);
        float2 vb = *(const float2*)(ar + 8);
        float2 vd = *(const float2*)(ar + 8 * RS + 8);
        uint32_t ah[4], al[4];
        ah[0] = pkb(va.x, va.y); al[0] = pkb(va.x - lof(ah[0]), va.y - hif(ah[0]));
        ah[1] = pkb(vc.x, vc.y); al[1] = pkb(vc.x - lof(ah[1]), vc.y - hif(ah[1]));
        ah[2] = pkb(vb.x, vb.y); al[2] = pkb(vb.x - lof(ah[2]), vb.y - hif(ah[2]));
        ah[3] = pkb(vd.x, vd.y); al[3] = pkb(vd.x - lof(ah[3]), vd.y - hif(ah[3]));
#pragma unroll
        for (int nt = 0; nt < Nt; nt++) {
            uint4 B = Wf[(nt * Kt + kt) * 32 + lane];
            mma16(acc[nt], ah, B.x, B.y);
            mma16(acc[nt], al, B.x, B.y);
            mma16(acc[nt], ah, B.z, B.w);
        }
    }
}

// relu layer over MT m-tiles: reads cols 0..K-1, writes relu(acc+bias) cols 0..N-1
template<int K, int N, int MT>
__device__ __forceinline__ void layer_relu(const uint4* __restrict__ Wf,
                                           const float* __restrict__ bias,
                                           float* __restrict__ Aw, int lane)
{
    constexpr int Nt = N / 8;
    const int g = lane >> 2, tig = lane & 3;
#pragma unroll
    for (int m = 0; m < MT; m++) {
        float acc[Nt][4];
        mma_compute<K, N>(Wf, Aw, m, lane, acc);
        __syncwarp();
        float* s0 = Aw + (16 * m + g) * RS + 2 * tig;
#pragma unroll
        for (int nt = 0; nt < Nt; nt++) {
            float b0 = bias[nt * 8 + 2 * tig], b1 = bias[nt * 8 + 2 * tig + 1];
            *(float2*)(s0 + nt * 8) =
                make_float2(fmaxf(acc[nt][0] + b0, 0.f), fmaxf(acc[nt][1] + b1, 0.f));
            *(float2*)(s0 + 8 * RS + nt * 8) =
                make_float2(fmaxf(acc[nt][2] + b0, 0.f), fmaxf(acc[nt][3] + b1, 0.f));
        }
        __syncwarp();
    }
}

// density layer 2: 64 -> 16, no relu, writes cols 16..31
template<int MT>
__device__ __forceinline__ void layer_l2(const uint4* __restrict__ Wf,
                                         const float* __restrict__ bias,
                                         float* __restrict__ Aw, int lane)
{
    const int g = lane >> 2, tig = lane & 3;
#pragma unroll
    for (int m = 0; m < MT; m++) {
        float acc[2][4];
        mma_compute<64, 16>(Wf, Aw, m, lane, acc);
        __syncwarp();
        float* s0 = Aw + (16 * m + g) * RS + 16 + 2 * tig;
#pragma unroll
        for (int nt = 0; nt < 2; nt++) {
            float b0 = bias[nt * 8 + 2 * tig], b1 = bias[nt * 8 + 2 * tig + 1];
            *(float2*)(s0 + nt * 8) = make_float2(acc[nt][0] + b0, acc[nt][1] + b1);
            *(float2*)(s0 + 8 * RS + nt * 8) = make_float2(acc[nt][2] + b0, acc[nt][3] + b1);
        }
        __syncwarp();
    }
}

__device__ __forceinline__ float sigm(float v) { return 1.f / (1.f + expf(-v)); }

template<int MT>
__device__ __forceinline__ void layer_c4(const uint4* __restrict__ Wf,
                                         const float* __restrict__ bias,
                                         const float* __restrict__ Aw, int lane,
                                         float* __restrict__ out, int pbase)
{
    const int g = lane >> 2, tig = lane & 3;
#pragma unroll
    for (int m = 0; m < MT; m++) {
        float acc[1][4];
        mma_compute<64, 8>(Wf, Aw, m, lane, acc);
        int r0 = pbase + 16 * m + g;
        int c = 2 * tig;
        if (c < 3) {
            float b = bias[c];
            out[NPTS + 3 * r0 + c]       = sigm(acc[0][0] + b);
            out[NPTS + 3 * (r0 + 8) + c] = sigm(acc[0][2] + b);
        }
        if (c + 1 < 3) {
            float b = bias[c + 1];
            out[NPTS + 3 * r0 + c + 1]       = sigm(acc[0][1] + b);
            out[NPTS + 3 * (r0 + 8) + c + 1] = sigm(acc[0][3] + b);
        }
    }
    __syncwarp();
}

__device__ __forceinline__ void stage_w(uint4* __restrict__ dst, const float* __restrict__ w,
                                        int Kt, int Nt, int rN, int tid)
{
    int tot = Kt * Nt * 32;
    for (int idx = tid; idx < tot; idx += THREADS) {
        int lane = idx & 31, f = idx >> 5;
        int kt = f % Kt, nt = f / Kt;
        int g = lane >> 2, tig = lane & 3;
        int n = nt * 8 + g;
        int k0 = kt * 16 + 2 * tig;
        float w00 = 0.f, w01 = 0.f, w10 = 0.f, w11 = 0.f;
        if (n < rN) {
            w00 = w[k0 * rN + n];       w01 = w[(k0 + 1) * rN + n];
            w10 = w[(k0 + 8) * rN + n]; w11 = w[(k0 + 9) * rN + n];
        }
        uint32_t h0 = pkb(w00, w01), h1 = pkb(w10, w11);
        uint32_t l0 = pkb(w00 - lof(h0), w01 - hif(h0));
        uint32_t l1 = pkb(w10 - lof(h1), w11 - hif(h1));
        dst[idx] = make_uint4(h0, h1, l0, l1);
    }
}

// hash-encode one point, write 32 features to its staging row
__device__ __forceinline__ void hash_point(const u64* __restrict__ emb,
                                           float cx, float cy, float cz,
                                           float* __restrict__ frow)
{
#pragma unroll 4
    for (int l = 0; l < 16; l++) {
        const float r = RESV[l];
        float fx = cx * r, fy = cy * r, fz = cz * r;
        float xf = floorf(fx), yf = floorf(fy), zf = floorf(fz);
        float tx = fx - xf, ty = fy - yf, tz = fz - zf;
        uint32_t px = (uint32_t)xf, py = (uint32_t)yf, pz = (uint32_t)zf;
        uint32_t hx0 = px,                hx1 = px + 1u;
        uint32_t hy0 = py * 2654435761u,  hy1 = hy0 + 2654435761u;
        uint32_t hz0 = pz * 805459861u,   hz1 = hz0 + 805459861u;
        const u64* tt = emb + ((size_t)l << 19);
        u64 e000 = __ldg(tt + ((hx0 ^ hy0 ^ hz0) & TMASK));
        u64 e001 = __ldg(tt + ((hx0 ^ hy0 ^ hz1) & TMASK));
        u64 e010 = __ldg(tt + ((hx0 ^ hy1 ^ hz0) & TMASK));
        u64 e011 = __ldg(tt + ((hx0 ^ hy1 ^ hz1) & TMASK));
        u64 e100 = __ldg(tt + ((hx1 ^ hy0 ^ hz0) & TMASK));
        u64 e101 = __ldg(tt + ((hx1 ^ hy0 ^ hz1) & TMASK));
        u64 e110 = __ldg(tt + ((hx1 ^ hy1 ^ hz0) & TMASK));
        u64 e111 = __ldg(tt + ((hx1 ^ hy1 ^ hz1) & TMASK));

        float ux = 1.f - tx, uy = 1.f - ty, uz = 1.f - tz;
        float w00 = ux * uy, w01 = ux * ty, w10 = tx * uy, w11 = tx * ty;
        float2 v; float a0 = 0.f, a1 = 0.f, w;
        w = w00 * uz; v = *(float2*)&e000; a0 = fmaf(w, v.x, a0); a1 = fmaf(w, v.y, a1);
        w = w00 * tz; v = *(float2*)&e001; a0 = fmaf(w, v.x, a0); a1 = fmaf(w, v.y, a1);
        w = w01 * uz; v = *(float2*)&e010; a0 = fmaf(w, v.x, a0); a1 = fmaf(w, v.y, a1);
        w = w01 * tz; v = *(float2*)&e011; a0 = fmaf(w, v.x, a0); a1 = fmaf(w, v.y, a1);
        w = w10 * uz; v = *(float2*)&e100; a0 = fmaf(w, v.x, a0); a1 = fmaf(w, v.y, a1);
        w = w10 * tz; v = *(float2*)&e101; a0 = fmaf(w, v.x, a0); a1 = fmaf(w, v.y, a1);
        w = w11 * uz; v = *(float2*)&e110; a0 = fmaf(w, v.x, a0); a1 = fmaf(w, v.y, a1);
        w = w11 * tz; v = *(float2*)&e111; a0 = fmaf(w, v.x, a0); a1 = fmaf(w, v.y, a1);
        *(float2*)(frow + 2 * l) = make_float2(a0, a1);
    }
}

// SH deg-4 of normalized dir -> staging cols 0..15
__device__ __forceinline__ void sh_write(const float* __restrict__ dirs, int p,
                                         float* __restrict__ frow)
{
    float dxr = dirs[3 * p + 0];
    float dyr = dirs[3 * p + 1];
    float dzr = dirs[3 * p + 2];
    float nrm = sqrtf(dxr * dxr + dyr * dyr + dzr * dzr);
    float x = dxr / nrm, y = dyr / nrm, z = dzr / nrm;
    x = ((x + 1.f) * 0.5f) * 2.f - 1.f;
    y = ((y + 1.f) * 0.5f) * 2.f - 1.f;
    z = ((z + 1.f) * 0.5f) * 2.f - 1.f;
    float xx = x * x, yy = y * y, zz = z * z;
    float xy = x * y, yz = y * z, xz = x * z;
    *(float4*)(frow + 0) = make_float4(
        0.28209479177387814f,
        -0.48860251190291987f * y,
         0.48860251190291987f * z,
        -0.48860251190291987f * x);
    *(float4*)(frow + 4) = make_float4(
         1.0925484305920792f * xy,
        -1.0925484305920792f * yz,
         0.94617469575756f * zz - 0.31539156525252f,
        -1.0925484305920792f * xz);
    *(float4*)(frow + 8) = make_float4(
         0.5462742152960396f * (xx - yy),
         0.5900435899266435f * y * (-3.0f * xx + yy),
         2.890611442640554f * xy * z,
         0.4570457994644657f * y * (1.0f - 5.0f * zz));
    *(float4*)(frow + 12) = make_float4(
         0.3731763325901154f * z * (5.0f * zz - 3.0f),
         0.4570457994644657f * x * (1.0f - 5.0f * zz),
         1.445305721320277f * z * (xx - yy),
         0.5900435899266435f * x * (xx - 3.0f * yy));
}

__global__ void __launch_bounds__(THREADS, 1)
nerf_mma_kernel(const float* __restrict__ coords,
                const float* __restrict__ dirs,
                const u64*   __restrict__ emb,
                const float* __restrict__ dw1, const float* __restrict__ db1,
                const float* __restrict__ dw2, const float* __restrict__ db2,
                const float* __restrict__ cw1, const float* __restrict__ cb1,
                const float* __restrict__ cw2, const float* __restrict__ cb2,
                const float* __restrict__ cw3, const float* __restrict__ cb3,
                const float* __restrict__ cw4, const float* __restrict__ cb4,
                float* __restrict__ out)
{
    extern __shared__ float sm[];
    uint4* wf = (uint4*)sm;
    const int tid = threadIdx.x;

    stage_w(wf + WF_L1, dw1, 2, 8, 64, tid);
    stage_w(wf + WF_L2, dw2, 4, 2, 16, tid);
    stage_w(wf + WF_C1, cw1, 2, 8, 64, tid);
    stage_w(wf + WF_C2, cw2, 4, 8, 64, tid);
    stage_w(wf + WF_C3, cw3, 4, 8, 64, tid);
    stage_w(wf + WF_C4, cw4, 4, 1,  3, tid);
    for (int i = tid; i < 64; i += THREADS) sm[BIAS_F + i] = db1[i];
    for (int i = tid; i < 16; i += THREADS) sm[BIAS_F + 64 + i] = db2[i];
    for (int i = tid; i < 64; i += THREADS) sm[BIAS_F + 80 + i] = cb1[i];
    for (int i = tid; i < 64; i += THREADS) sm[BIAS_F + 144 + i] = cb2[i];
    for (int i = tid; i < 64; i += THREADS) sm[BIAS_F + 208 + i] = cb3[i];
    for (int i = tid; i < 8;  i += THREADS) sm[BIAS_F + 272 + i] = (i < 3) ? cb4[i] : 0.f;
    __syncthreads();

    const int lane = tid & 31, warp = tid >> 5;
    float* Aw = sm + STG_F + warp * (64 * RS);
    float* frow0 = Aw + lane * RS;
    float* frow1 = Aw + (lane + 32) * RS;

    for (;;) {
        unsigned wt;
        if (lane == 0) wt = atomicAdd(&g_tile_ctr, 1u);
        wt = __shfl_sync(0xFFFFFFFFu, wt, 0);
        if (wt >= NT64) break;

        const int p0 = (int)wt * 64 + lane;
        const int p1 = p0 + 32;

        // ---------- hash-grid encode: 2 points per lane ----------
        {
            float cx0 = coords[3 * p0], cy0 = coords[3 * p0 + 1], cz0 = coords[3 * p0 + 2];
            float cx1 = coords[3 * p1], cy1 = coords[3 * p1 + 1], cz1 = coords[3 * p1 + 2];
            hash_point(emb, cx0, cy0, cz0, frow0);
            hash_point(emb, cx1, cy1, cz1, frow1);
        }
        __syncwarp();

        // ---------- density MLP ----------
        layer_relu<32, 64, 4>(wf + WF_L1, sm + BIAS_F, Aw, lane);
        layer_l2<4>(wf + WF_L2, sm + BIAS_F + 64, Aw, lane);

        out[p0] = expf(frow0[16]);
        out[p1] = expf(frow1[16]);

        // ---------- SH deg-4 into cols 0..15 ----------
        sh_write(dirs, p0, frow0);
        sh_write(dirs, p1, frow1);
        __syncwarp();

        // ---------- color MLP ----------
        layer_relu<32, 64, 4>(wf + WF_C1, sm + BIAS_F + 80,  Aw, lane);
        layer_relu<64, 64, 4>(wf + WF_C2, sm + BIAS_F + 144, Aw, lane);
        layer_relu<64, 64, 4>(wf + WF_C3, sm + BIAS_F + 208, Aw, lane);
        layer_c4<4>(wf + WF_C4, sm + BIAS_F + 272, Aw, lane, out, (int)wt * 64);
    }
}

extern "C" void kernel_launch(void* const* d_in, const int* in_sizes, int n_in,
                              void* d_out, int out_size)
{
    const float* coords = (const float*)d_in[0];
    const float* dirs   = (const float*)d_in[1];
    const u64*   emb    = (const u64*)d_in[2];
    const float* dw1 = (const float*)d_in[3];
    const float* db1 = (const float*)d_in[4];
    const float* dw2 = (const float*)d_in[5];
    const float* db2 = (const float*)d_in[6];
    const float* cw1 = (const float*)d_in[7];
    const float* cb1 = (const float*)d_in[8];
    const float* cw2 = (const float*)d_in[9];
    const float* cb2 = (const float*)d_in[10];
    const float* cw3 = (const float*)d_in[11];
    const float* cb3 = (const float*)d_in[12];
    const float* cw4 = (const float*)d_in[13];
    const float* cb4 = (const float*)d_in[14];
    float* out = (float*)d_out;

    cudaFuncSetAttribute(nerf_mma_kernel,
                         cudaFuncAttributeMaxDynamicSharedMemorySize, SMEM_BYTES);

    zero_ctr_kernel<<<1, 1>>>();
    nerf_mma_kernel<<<NCTA, THREADS, SMEM_BYTES>>>(
        coords, dirs, emb,
        dw1, db1, dw2, db2,
        cw1, cb1, cw2, cb2, cw3, cb3, cw4, cb4,
        out);
}

// round 11
// speedup vs baseline: 2.0822x; 1.6453x over previous
#include <cuda_runtime.h>
#include <stdint.h>

#define NPTS    262144
#define NWTILES 8192          // warp-tiles of 32 points
#define TMASK   0x7FFFFu
#define RS      72            // staging row stride (floats); banks 8g+2tig conflict-free
#define THREADS 384
#define NWARP   12
#define NCTA    148

// weight fragment arrays (uint4 units)
#define WF_L1 0               // Kt2 Nt8 -> 512
#define WF_L2 512             // Kt4 Nt2 -> 256
#define WF_C1 768             // Kt2 Nt8 -> 512
#define WF_C2 1280            // Kt4 Nt8 -> 1024
#define WF_C3 2304            // Kt4 Nt8 -> 1024
#define WF_C4 3328            // Kt4 Nt1 -> 128
#define WF_TOT 3456
#define BIAS_F (WF_TOT * 4)   // float idx 13824
#define STG_F  (BIAS_F + 280) // 14104, 16B aligned
#define SMEM_FLOATS (STG_F + NWARP * 32 * RS)
#define SMEM_BYTES  (SMEM_FLOATS * 4)

typedef unsigned long long u64;

__device__ unsigned int g_tile_ctr;
__global__ void zero_ctr_kernel() { g_tile_ctr = 0u; }

__device__ __forceinline__ uint32_t pkb(float lo, float hi) {
    uint32_t r; asm("cvt.rn.bf16x2.f32 %0, %1, %2;" : "=r"(r) : "f"(hi), "f"(lo)); return r;
}
__device__ __forceinline__ float lof(uint32_t u) { return __uint_as_float(u << 16); }
__device__ __forceinline__ float hif(uint32_t u) { return __uint_as_float(u & 0xffff0000u); }

__device__ __forceinline__ void mma16(float* d, const uint32_t* a, uint32_t b0, uint32_t b1) {
    asm volatile(
        "mma.sync.aligned.m16n8k16.row.col.f32.bf16.bf16.f32 "
        "{%0,%1,%2,%3},{%4,%5,%6,%7},{%8,%9},{%0,%1,%2,%3};"
        : "+f"(d[0]), "+f"(d[1]), "+f"(d[2]), "+f"(d[3])
        : "r"(a[0]), "r"(a[1]), "r"(a[2]), "r"(a[3]), "r"(b0), "r"(b1));
}

// acc[Nt][4] = A(16xK fp32 staging) @ W(KxN), 3-pass bf16 (AhBh + AlBh + AhBl)
template<int K, int N>
__device__ __forceinline__ void mma_compute(const uint4* __restrict__ Wf,
                                            const float* __restrict__ Aw,
                                            int m, int lane, float acc[N / 8][4])
{
    constexpr int Kt = K / 16, Nt = N / 8;
    const int g = lane >> 2, tig = lane & 3;
#pragma unroll
    for (int nt = 0; nt < Nt; nt++)
        acc[nt][0] = acc[nt][1] = acc[nt][2] = acc[nt][3] = 0.f;
    const float* base = Aw + (16 * m + g) * RS + 2 * tig;
#pragma unroll
    for (int kt = 0; kt < Kt; kt++) {
        const float* ar = base + kt * 16;
        float2 va = *(const float2*)(ar);
        float2 vc = *(const float2*)(ar + 8 * RS);
        float2 vb = *(const float2*)(ar + 8);
        float2 vd = *(const float2*)(ar + 8 * RS + 8);
        uint32_t ah[4], al[4];
        ah[0] = pkb(va.x, va.y); al[0] = pkb(va.x - lof(ah[0]), va.y - hif(ah[0]));
        ah[1] = pkb(vc.x, vc.y); al[1] = pkb(vc.x - lof(ah[1]), vc.y - hif(ah[1]));
        ah[2] = pkb(vb.x, vb.y); al[2] = pkb(vb.x - lof(ah[2]), vb.y - hif(ah[2]));
        ah[3] = pkb(vd.x, vd.y); al[3] = pkb(vd.x - lof(ah[3]), vd.y - hif(ah[3]));
#pragma unroll
        for (int nt = 0; nt < Nt; nt++) {
            uint4 B = Wf[(nt * Kt + kt) * 32 + lane];
            mma16(acc[nt], ah, B.x, B.y);
            mma16(acc[nt], al, B.x, B.y);
            mma16(acc[nt], ah, B.z, B.w);
        }
    }
}

// relu layer: compute m-tile, sync, store; single trailing sync for next layer
template<int K, int N>
__device__ __forceinline__ void layer_relu(const uint4* __restrict__ Wf,
                                           const float* __restrict__ bias,
                                           float* __restrict__ Aw, int lane)
{
    constexpr int Nt = N / 8;
    const int g = lane >> 2, tig = lane & 3;
#pragma unroll
    for (int m = 0; m < 2; m++) {
        float acc[Nt][4];
        mma_compute<K, N>(Wf, Aw, m, lane, acc);
        __syncwarp();   // all lanes done reading this m-tile's rows before overwrite
        float* s0 = Aw + (16 * m + g) * RS + 2 * tig;
#pragma unroll
        for (int nt = 0; nt < Nt; nt++) {
            float b0 = bias[nt * 8 + 2 * tig], b1 = bias[nt * 8 + 2 * tig + 1];
            *(float2*)(s0 + nt * 8) =
                make_float2(fmaxf(acc[nt][0] + b0, 0.f), fmaxf(acc[nt][1] + b1, 0.f));
            *(float2*)(s0 + 8 * RS + nt * 8) =
                make_float2(fmaxf(acc[nt][2] + b0, 0.f), fmaxf(acc[nt][3] + b1, 0.f));
        }
        // no sync here: m1 compute reads rows 16..31, disjoint from m0's stores
    }
    __syncwarp();
}

// density layer 2: 64 -> 16, no relu, writes cols 16..31
__device__ __forceinline__ void layer_l2(const uint4* __restrict__ Wf,
                                         const float* __restrict__ bias,
                                         float* __restrict__ Aw, int lane)
{
    const int g = lane >> 2, tig = lane & 3;
#pragma unroll
    for (int m = 0; m < 2; m++) {
        float acc[2][4];
        mma_compute<64, 16>(Wf, Aw, m, lane, acc);
        __syncwarp();
        float* s0 = Aw + (16 * m + g) * RS + 16 + 2 * tig;
#pragma unroll
        for (int nt = 0; nt < 2; nt++) {
            float b0 = bias[nt * 8 + 2 * tig], b1 = bias[nt * 8 + 2 * tig + 1];
            *(float2*)(s0 + nt * 8) = make_float2(acc[nt][0] + b0, acc[nt][1] + b1);
            *(float2*)(s0 + 8 * RS + nt * 8) = make_float2(acc[nt][2] + b0, acc[nt][3] + b1);
        }
    }
    __syncwarp();
}

__device__ __forceinline__ float sigm(float v) { return 1.f / (1.f + expf(-v)); }

__device__ __forceinline__ void layer_c4(const uint4* __restrict__ Wf,
                                         const float* __restrict__ bias,
                                         const float* __restrict__ Aw, int lane,
                                         float* __restrict__ out, int pbase)
{
    const int g = lane >> 2, tig = lane & 3;
#pragma unroll
    for (int m = 0; m < 2; m++) {
        float acc[1][4];
        mma_compute<64, 8>(Wf, Aw, m, lane, acc);
        int r0 = pbase + 16 * m + g;
        int c = 2 * tig;
        if (c < 3) {
            float b = bias[c];
            out[NPTS + 3 * r0 + c]       = sigm(acc[0][0] + b);
            out[NPTS + 3 * (r0 + 8) + c] = sigm(acc[0][2] + b);
        }
        if (c + 1 < 3) {
            float b = bias[c + 1];
            out[NPTS + 3 * r0 + c + 1]       = sigm(acc[0][1] + b);
            out[NPTS + 3 * (r0 + 8) + c + 1] = sigm(acc[0][3] + b);
        }
    }
    __syncwarp();   // protect staging reads from next tile's feature stores
}

__device__ __forceinline__ void stage_w(uint4* __restrict__ dst, const float* __restrict__ w,
                                        int Kt, int Nt, int rN, int tid)
{
    int tot = Kt * Nt * 32;
    for (int idx = tid; idx < tot; idx += THREADS) {
        int lane = idx & 31, f = idx >> 5;
        int kt = f % Kt, nt = f / Kt;
        int g = lane >> 2, tig = lane & 3;
        int n = nt * 8 + g;
        int k0 = kt * 16 + 2 * tig;
        float w00 = 0.f, w01 = 0.f, w10 = 0.f, w11 = 0.f;
        if (n < rN) {
            w00 = w[k0 * rN + n];       w01 = w[(k0 + 1) * rN + n];
            w10 = w[(k0 + 8) * rN + n]; w11 = w[(k0 + 9) * rN + n];
        }
        uint32_t h0 = pkb(w00, w01), h1 = pkb(w10, w11);
        uint32_t l0 = pkb(w00 - lof(h0), w01 - hif(h0));
        uint32_t l1 = pkb(w10 - lof(h1), w11 - hif(h1));
        dst[idx] = make_uint4(h0, h1, l0, l1);
    }
}

__global__ void __launch_bounds__(THREADS, 1)
nerf_mma_kernel(const float* __restrict__ coords,
                const float* __restrict__ dirs,
                const u64*   __restrict__ emb,
                const float* __restrict__ dw1, const float* __restrict__ db1,
                const float* __restrict__ dw2, const float* __restrict__ db2,
                const float* __restrict__ cw1, const float* __restrict__ cb1,
                const float* __restrict__ cw2, const float* __restrict__ cb2,
                const float* __restrict__ cw3, const float* __restrict__ cb3,
                const float* __restrict__ cw4, const float* __restrict__ cb4,
                float* __restrict__ out)
{
    extern __shared__ float sm[];
    uint4* wf = (uint4*)sm;
    const int tid = threadIdx.x;

    stage_w(wf + WF_L1, dw1, 2, 8, 64, tid);
    stage_w(wf + WF_L2, dw2, 4, 2, 16, tid);
    stage_w(wf + WF_C1, cw1, 2, 8, 64, tid);
    stage_w(wf + WF_C2, cw2, 4, 8, 64, tid);
    stage_w(wf + WF_C3, cw3, 4, 8, 64, tid);
    stage_w(wf + WF_C4, cw4, 4, 1,  3, tid);
    for (int i = tid; i < 64; i += THREADS) sm[BIAS_F + i] = db1[i];
    for (int i = tid; i < 16; i += THREADS) sm[BIAS_F + 64 + i] = db2[i];
    for (int i = tid; i < 64; i += THREADS) sm[BIAS_F + 80 + i] = cb1[i];
    for (int i = tid; i < 64; i += THREADS) sm[BIAS_F + 144 + i] = cb2[i];
    for (int i = tid; i < 64; i += THREADS) sm[BIAS_F + 208 + i] = cb3[i];
    for (int i = tid; i < 8;  i += THREADS) sm[BIAS_F + 272 + i] = (i < 3) ? cb4[i] : 0.f;
    __syncthreads();

    const int lane = tid & 31, warp = tid >> 5;
    float* Aw = sm + STG_F + warp * (32 * RS);
    float* frow = Aw + lane * RS;

    const float RESV[16] = {16.f, 20.f, 25.f, 32.f, 40.f, 50.f, 64.f, 80.f,
                            101.f, 128.f, 161.f, 203.f, 256.f, 322.f, 406.f, 512.f};

    // initial steal
    unsigned wt;
    if (lane == 0) wt = atomicAdd(&g_tile_ctr, 1u);
    wt = __shfl_sync(0xFFFFFFFFu, wt, 0);

    while (wt < NWTILES) {
        const int p = (int)wt * 32 + lane;

        // ---------- hash-grid encode (1 point per lane) ----------
        const float cx = coords[3 * p + 0];
        const float cy = coords[3 * p + 1];
        const float cz = coords[3 * p + 2];
        float dxr = dirs[3 * p + 0];
        float dyr = dirs[3 * p + 1];
        float dzr = dirs[3 * p + 2];

#pragma unroll
        for (int l = 0; l < 16; l++) {
            const float r = RESV[l];
            float fx = cx * r, fy = cy * r, fz = cz * r;
            float xf = floorf(fx), yf = floorf(fy), zf = floorf(fz);
            float tx = fx - xf, ty = fy - yf, tz = fz - zf;
            uint32_t px = (uint32_t)xf, py = (uint32_t)yf, pz = (uint32_t)zf;
            uint32_t hx0 = px,                hx1 = px + 1u;
            uint32_t hy0 = py * 2654435761u,  hy1 = hy0 + 2654435761u;
            uint32_t hz0 = pz * 805459861u,   hz1 = hz0 + 805459861u;
            const u64* tt = emb + ((size_t)l << 19);
            u64 e000 = __ldg(tt + ((hx0 ^ hy0 ^ hz0) & TMASK));
            u64 e001 = __ldg(tt + ((hx0 ^ hy0 ^ hz1) & TMASK));
            u64 e010 = __ldg(tt + ((hx0 ^ hy1 ^ hz0) & TMASK));
            u64 e011 = __ldg(tt + ((hx0 ^ hy1 ^ hz1) & TMASK));
            u64 e100 = __ldg(tt + ((hx1 ^ hy0 ^ hz0) & TMASK));
            u64 e101 = __ldg(tt + ((hx1 ^ hy0 ^ hz1) & TMASK));
            u64 e110 = __ldg(tt + ((hx1 ^ hy1 ^ hz0) & TMASK));
            u64 e111 = __ldg(tt + ((hx1 ^ hy1 ^ hz1) & TMASK));

            float ux = 1.f - tx, uy = 1.f - ty, uz = 1.f - tz;
            float w00 = ux * uy, w01 = ux * ty, w10 = tx * uy, w11 = tx * ty;
            float2 v; float a0 = 0.f, a1 = 0.f, w;
            w = w00 * uz; v = *(float2*)&e000; a0 = fmaf(w, v.x, a0); a1 = fmaf(w, v.y, a1);
            w = w00 * tz; v = *(float2*)&e001; a0 = fmaf(w, v.x, a0); a1 = fmaf(w, v.y, a1);
            w = w01 * uz; v = *(float2*)&e010; a0 = fmaf(w, v.x, a0); a1 = fmaf(w, v.y, a1);
            w = w01 * tz; v = *(float2*)&e011; a0 = fmaf(w, v.x, a0); a1 = fmaf(w, v.y, a1);
            w = w10 * uz; v = *(float2*)&e100; a0 = fmaf(w, v.x, a0); a1 = fmaf(w, v.y, a1);
            w = w10 * tz; v = *(float2*)&e101; a0 = fmaf(w, v.x, a0); a1 = fmaf(w, v.y, a1);
            w = w11 * uz; v = *(float2*)&e110; a0 = fmaf(w, v.x, a0); a1 = fmaf(w, v.y, a1);
            w = w11 * tz; v = *(float2*)&e111; a0 = fmaf(w, v.x, a0); a1 = fmaf(w, v.y, a1);
            *(float2*)(frow + 2 * l) = make_float2(a0, a1);
        }
        __syncwarp();

        // steal next tile now; ATOMG latency hides under the density MLP
        unsigned wt_next;
        if (lane == 0) wt_next = atomicAdd(&g_tile_ctr, 1u);

        // ---------- density MLP ----------
        layer_relu<32, 64>(wf + WF_L1, sm + BIAS_F, Aw, lane);
        layer_l2(wf + WF_L2, sm + BIAS_F + 64, Aw, lane);

        out[p] = expf(frow[16]);

        // ---------- SH deg-4 into cols 0..15 ----------
        {
            float nrm = sqrtf(dxr * dxr + dyr * dyr + dzr * dzr);
            float x = dxr / nrm, y = dyr / nrm, z = dzr / nrm;
            x = ((x + 1.f) * 0.5f) * 2.f - 1.f;
            y = ((y + 1.f) * 0.5f) * 2.f - 1.f;
            z = ((z + 1.f) * 0.5f) * 2.f - 1.f;
            float xx = x * x, yy = y * y, zz = z * z;
            float xy = x * y, yz = y * z, xz = x * z;
            *(float4*)(frow + 0) = make_float4(
                0.28209479177387814f,
                -0.48860251190291987f * y,
                 0.48860251190291987f * z,
                -0.48860251190291987f * x);
            *(float4*)(frow + 4) = make_float4(
                 1.0925484305920792f * xy,
                -1.0925484305920792f * yz,
                 0.94617469575756f * zz - 0.31539156525252f,
                -1.0925484305920792f * xz);
            *(float4*)(frow + 8) = make_float4(
                 0.5462742152960396f * (xx - yy),
                 0.5900435899266435f * y * (-3.0f * xx + yy),
                 2.890611442640554f * xy * z,
                 0.4570457994644657f * y * (1.0f - 5.0f * zz));
            *(float4*)(frow + 12) = make_float4(
                 0.3731763325901154f * z * (5.0f * zz - 3.0f),
                 0.4570457994644657f * x * (1.0f - 5.0f * zz),
                 1.445305721320277f * z * (xx - yy),
                 0.5900435899266435f * x * (xx - 3.0f * yy));
        }
        __syncwarp();

        // ---------- color MLP ----------
        layer_relu<32, 64>(wf + WF_C1, sm + BIAS_F + 80,  Aw, lane);
        layer_relu<64, 64>(wf + WF_C2, sm + BIAS_F + 144, Aw, lane);
        layer_relu<64, 64>(wf + WF_C3, sm + BIAS_F + 208, Aw, lane);
        layer_c4(wf + WF_C4, sm + BIAS_F + 272, Aw, lane, out, (int)wt * 32);

        wt = __shfl_sync(0xFFFFFFFFu, wt_next, 0);
    }
}

extern "C" void kernel_launch(void* const* d_in, const int* in_sizes, int n_in,
                              void* d_out, int out_size)
{
    const float* coords = (const float*)d_in[0];
    const float* dirs   = (const float*)d_in[1];
    const u64*   emb    = (const u64*)d_in[2];
    const float* dw1 = (const float*)d_in[3];
    const float* db1 = (const float*)d_in[4];
    const float* dw2 = (const float*)d_in[5];
    const float* db2 = (const float*)d_in[6];
    const float* cw1 = (const float*)d_in[7];
    const float* cb1 = (const float*)d_in[8];
    const float* cw2 = (const float*)d_in[9];
    const float* cb2 = (const float*)d_in[10];
    const float* cw3 = (const float*)d_in[11];
    const float* cb3 = (const float*)d_in[12];
    const float* cw4 = (const float*)d_in[13];
    const float* cb4 = (const float*)d_in[14];
    float* out = (float*)d_out;

    cudaFuncSetAttribute(nerf_mma_kernel,
                         cudaFuncAttributeMaxDynamicSharedMemorySize, SMEM_BYTES);

    zero_ctr_kernel<<<1, 1>>>();
    nerf_mma_kernel<<<NCTA, THREADS, SMEM_BYTES>>>(
        coords, dirs, emb,
        dw1, db1, dw2, db2,
        cw1, cb1, cw2, cb2, cw3, cb3, cw4, cb4,
        out);
}

// round 12
// speedup vs baseline: 2.1421x; 1.0288x over previous
#include <cuda_runtime.h>
#include <stdint.h>

#define NPTS    262144
#define NWTILES 8192          // warp-tiles of 32 points
#define TMASK   0x7FFFFu
#define RS      72            // staging row stride (floats); conflict-free A-frag loads
#define THREADS 384
#define NWARP   12
#define NCTA    148

// weight fragment arrays (uint4 units)
#define WF_L1 0               // Kt2 Nt8 -> 512
#define WF_L2 512             // Kt4 Nt2 -> 256
#define WF_C1 768             // Kt2 Nt8 -> 512
#define WF_C2 1280            // Kt4 Nt8 -> 1024
#define WF_C3 2304            // Kt4 Nt8 -> 1024
#define WF_C4 3328            // Kt4 Nt1 -> 128
#define WF_TOT 3456
#define BIAS_F (WF_TOT * 4)   // float idx 13824
#define STG_F  (BIAS_F + 280) // 14104, 16B aligned
#define SMEM_FLOATS (STG_F + NWARP * 32 * RS)
#define SMEM_BYTES  (SMEM_FLOATS * 4)

typedef unsigned long long u64;

__device__ __forceinline__ uint32_t pkb(float lo, float hi) {
    uint32_t r; asm("cvt.rn.bf16x2.f32 %0, %1, %2;" : "=r"(r) : "f"(hi), "f"(lo)); return r;
}
__device__ __forceinline__ float lof(uint32_t u) { return __uint_as_float(u << 16); }
__device__ __forceinline__ float hif(uint32_t u) { return __uint_as_float(u & 0xffff0000u); }

__device__ __forceinline__ void mma16(float* d, const uint32_t* a, uint32_t b0, uint32_t b1) {
    asm volatile(
        "mma.sync.aligned.m16n8k16.row.col.f32.bf16.bf16.f32 "
        "{%0,%1,%2,%3},{%4,%5,%6,%7},{%8,%9},{%0,%1,%2,%3};"
        : "+f"(d[0]), "+f"(d[1]), "+f"(d[2]), "+f"(d[3])
        : "r"(a[0]), "r"(a[1]), "r"(a[2]), "r"(a[3]), "r"(b0), "r"(b1));
}

// acc[Nt][4] = A(16xK fp32 staging) @ W(KxN), 3-pass bf16 (AhBh + AlBh + AhBl)
template<int K, int N>
__device__ __forceinline__ void mma_compute(const uint4* __restrict__ Wf,
                                            const float* __restrict__ Aw,
                                            int m, int lane, float acc[N / 8][4])
{
    constexpr int Kt = K / 16, Nt = N / 8;
    const int g = lane >> 2, tig = lane & 3;
#pragma unroll
    for (int nt = 0; nt < Nt; nt++)
        acc[nt][0] = acc[nt][1] = acc[nt][2] = acc[nt][3] = 0.f;
    const float* base = Aw + (16 * m + g) * RS + 2 * tig;
#pragma unroll
    for (int kt = 0; kt < Kt; kt++) {
        const float* ar = base + kt * 16;
        float2 va = *(const float2*)(ar);
        float2 vc = *(const float2*)(ar + 8 * RS);
        float2 vb = *(const float2*)(ar + 8);
        float2 vd = *(const float2*)(ar + 8 * RS + 8);
        uint32_t ah[4], al[4];
        ah[0] = pkb(va.x, va.y); al[0] = pkb(va.x - lof(ah[0]), va.y - hif(ah[0]));
        ah[1] = pkb(vc.x, vc.y); al[1] = pkb(vc.x - lof(ah[1]), vc.y - hif(ah[1]));
        ah[2] = pkb(vb.x, vb.y); al[2] = pkb(vb.x - lof(ah[2]), vb.y - hif(ah[2]));
        ah[3] = pkb(vd.x, vd.y); al[3] = pkb(vd.x - lof(ah[3]), vd.y - hif(ah[3]));
#pragma unroll
        for (int nt = 0; nt < Nt; nt++) {
            uint4 B = Wf[(nt * Kt + kt) * 32 + lane];
            mma16(acc[nt], ah, B.x, B.y);
            mma16(acc[nt], al, B.x, B.y);
            mma16(acc[nt], ah, B.z, B.w);
        }
    }
}

template<int K, int N>
__device__ __forceinline__ void layer_relu(const uint4* __restrict__ Wf,
                                           const float* __restrict__ bias,
                                           float* __restrict__ Aw, int lane)
{
    constexpr int Nt = N / 8;
    const int g = lane >> 2, tig = lane & 3;
#pragma unroll
    for (int m = 0; m < 2; m++) {
        float acc[Nt][4];
        mma_compute<K, N>(Wf, Aw, m, lane, acc);
        __syncwarp();
        float* s0 = Aw + (16 * m + g) * RS + 2 * tig;
#pragma unroll
        for (int nt = 0; nt < Nt; nt++) {
            float b0 = bias[nt * 8 + 2 * tig], b1 = bias[nt * 8 + 2 * tig + 1];
            *(float2*)(s0 + nt * 8) =
                make_float2(fmaxf(acc[nt][0] + b0, 0.f), fmaxf(acc[nt][1] + b1, 0.f));
            *(float2*)(s0 + 8 * RS + nt * 8) =
                make_float2(fmaxf(acc[nt][2] + b0, 0.f), fmaxf(acc[nt][3] + b1, 0.f));
        }
        // no sync: m1 reads rows 16..31, disjoint from m0's stores
    }
    __syncwarp();
}

// density layer 2: 64 -> 16, no relu, writes cols 16..31
__device__ __forceinline__ void layer_l2(const uint4* __restrict__ Wf,
                                         const float* __restrict__ bias,
                                         float* __restrict__ Aw, int lane)
{
    const int g = lane >> 2, tig = lane & 3;
#pragma unroll
    for (int m = 0; m < 2; m++) {
        float acc[2][4];
        mma_compute<64, 16>(Wf, Aw, m, lane, acc);
        __syncwarp();
        float* s0 = Aw + (16 * m + g) * RS + 16 + 2 * tig;
#pragma unroll
        for (int nt = 0; nt < 2; nt++) {
            float b0 = bias[nt * 8 + 2 * tig], b1 = bias[nt * 8 + 2 * tig + 1];
            *(float2*)(s0 + nt * 8) = make_float2(acc[nt][0] + b0, acc[nt][1] + b1);
            *(float2*)(s0 + 8 * RS + nt * 8) = make_float2(acc[nt][2] + b0, acc[nt][3] + b1);
        }
    }
    __syncwarp();
}

__device__ __forceinline__ float sigm(float v) { return 1.f / (1.f + expf(-v)); }

__device__ __forceinline__ void layer_c4(const uint4* __restrict__ Wf,
                                         const float* __restrict__ bias,
                                         const float* __restrict__ Aw, int lane,
                                         float* __restrict__ out, int pbase)
{
    const int g = lane >> 2, tig = lane & 3;
#pragma unroll
    for (int m = 0; m < 2; m++) {
        float acc[1][4];
        mma_compute<64, 8>(Wf, Aw, m, lane, acc);
        int r0 = pbase + 16 * m + g;
        int c = 2 * tig;
        if (c < 3) {
            float b = bias[c];
            out[NPTS + 3 * r0 + c]       = sigm(acc[0][0] + b);
            out[NPTS + 3 * (r0 + 8) + c] = sigm(acc[0][2] + b);
        }
        if (c + 1 < 3) {
            float b = bias[c + 1];
            out[NPTS + 3 * r0 + c + 1]       = sigm(acc[0][1] + b);
            out[NPTS + 3 * (r0 + 8) + c + 1] = sigm(acc[0][3] + b);
        }
    }
    __syncwarp();
}

__device__ __forceinline__ void stage_w(uint4* __restrict__ dst, const float* __restrict__ w,
                                        int Kt, int Nt, int rN, int tid)
{
    int tot = Kt * Nt * 32;
    for (int idx = tid; idx < tot; idx += THREADS) {
        int lane = idx & 31, f = idx >> 5;
        int kt = f % Kt, nt = f / Kt;
        int g = lane >> 2, tig = lane & 3;
        int n = nt * 8 + g;
        int k0 = kt * 16 + 2 * tig;
        float w00 = 0.f, w01 = 0.f, w10 = 0.f, w11 = 0.f;
        if (n < rN) {
            w00 = w[k0 * rN + n];       w01 = w[(k0 + 1) * rN + n];
            w10 = w[(k0 + 8) * rN + n]; w11 = w[(k0 + 9) * rN + n];
        }
        uint32_t h0 = pkb(w00, w01), h1 = pkb(w10, w11);
        uint32_t l0 = pkb(w00 - lof(h0), w01 - hif(h0));
        uint32_t l1 = pkb(w10 - lof(h1), w11 - hif(h1));
        dst[idx] = make_uint4(h0, h1, l0, l1);
    }
}

__global__ void __launch_bounds__(THREADS, 1)
nerf_mma_kernel(const float* __restrict__ coords,
                const float* __restrict__ dirs,
                const u64*   __restrict__ emb,
                const float* __restrict__ dw1, const float* __restrict__ db1,
                const float* __restrict__ dw2, const float* __restrict__ db2,
                const float* __restrict__ cw1, const float* __restrict__ cb1,
                const float* __restrict__ cw2, const float* __restrict__ cb2,
                const float* __restrict__ cw3, const float* __restrict__ cb3,
                const float* __restrict__ cw4, const float* __restrict__ cb4,
                float* __restrict__ out)
{
    extern __shared__ float sm[];
    uint4* wf = (uint4*)sm;
    const int tid = threadIdx.x;

    stage_w(wf + WF_L1, dw1, 2, 8, 64, tid);
    stage_w(wf + WF_L2, dw2, 4, 2, 16, tid);
    stage_w(wf + WF_C1, cw1, 2, 8, 64, tid);
    stage_w(wf + WF_C2, cw2, 4, 8, 64, tid);
    stage_w(wf + WF_C3, cw3, 4, 8, 64, tid);
    stage_w(wf + WF_C4, cw4, 4, 1,  3, tid);
    for (int i = tid; i < 64; i += THREADS) sm[BIAS_F + i] = db1[i];
    for (int i = tid; i < 16; i += THREADS) sm[BIAS_F + 64 + i] = db2[i];
    for (int i = tid; i < 64; i += THREADS) sm[BIAS_F + 80 + i] = cb1[i];
    for (int i = tid; i < 64; i += THREADS) sm[BIAS_F + 144 + i] = cb2[i];
    for (int i = tid; i < 64; i += THREADS) sm[BIAS_F + 208 + i] = cb3[i];
    for (int i = tid; i < 8;  i += THREADS) sm[BIAS_F + 272 + i] = (i < 3) ? cb4[i] : 0.f;
    __syncthreads();

    const int lane = tid & 31, warp = tid >> 5;
    float* Aw = sm + STG_F + warp * (32 * RS);
    float* frow = Aw + lane * RS;

    const float RESV[16] = {16.f, 20.f, 25.f, 32.f, 40.f, 50.f, 64.f, 80.f,
                            101.f, 128.f, 161.f, 203.f, 256.f, 322.f, 406.f, 512.f};

    for (int wt = blockIdx.x * NWARP + warp; wt < NWTILES; wt += NCTA * NWARP) {
        const int p = wt * 32 + lane;

        // ---------- hash-grid encode, 4-level load batching ----------
        const float cx = coords[3 * p + 0];
        const float cy = coords[3 * p + 1];
        const float cz = coords[3 * p + 2];
        float dxr = dirs[3 * p + 0];
        float dyr = dirs[3 * p + 1];
        float dzr = dirs[3 * p + 2];

#pragma unroll
        for (int lg = 0; lg < 4; lg++) {
            u64 eb[32];
            // phase 1: issue all 32 gathers for levels lg*4 .. lg*4+3
#pragma unroll
            for (int j = 0; j < 4; j++) {
                const int l = lg * 4 + j;
                const float r = RESV[l];
                uint32_t px = (uint32_t)floorf(cx * r);
                uint32_t py = (uint32_t)floorf(cy * r);
                uint32_t pz = (uint32_t)floorf(cz * r);
                uint32_t hx0 = px,                hx1 = px + 1u;
                uint32_t hy0 = py * 2654435761u,  hy1 = hy0 + 2654435761u;
                uint32_t hz0 = pz * 805459861u,   hz1 = hz0 + 805459861u;
                const u64* tt = emb + ((size_t)l << 19);
                eb[8 * j + 0] = __ldg(tt + ((hx0 ^ hy0 ^ hz0) & TMASK));
                eb[8 * j + 1] = __ldg(tt + ((hx0 ^ hy0 ^ hz1) & TMASK));
                eb[8 * j + 2] = __ldg(tt + ((hx0 ^ hy1 ^ hz0) & TMASK));
                eb[8 * j + 3] = __ldg(tt + ((hx0 ^ hy1 ^ hz1) & TMASK));
                eb[8 * j + 4] = __ldg(tt + ((hx1 ^ hy0 ^ hz0) & TMASK));
                eb[8 * j + 5] = __ldg(tt + ((hx1 ^ hy0 ^ hz1) & TMASK));
                eb[8 * j + 6] = __ldg(tt + ((hx1 ^ hy1 ^ hz0) & TMASK));
                eb[8 * j + 7] = __ldg(tt + ((hx1 ^ hy1 ^ hz1) & TMASK));
            }
            // phase 2: interpolate the 4 levels (weights recomputed, regs stay low)
#pragma unroll
            for (int j = 0; j < 4; j++) {
                const int l = lg * 4 + j;
                const float r = RESV[l];
                float fx = cx * r, fy = cy * r, fz = cz * r;
                float tx = fx - floorf(fx), ty = fy - floorf(fy), tz = fz - floorf(fz);
                float ux = 1.f - tx, uy = 1.f - ty, uz = 1.f - tz;
                float w00 = ux * uy, w01 = ux * ty, w10 = tx * uy, w11 = tx * ty;
                float2 v; float a0 = 0.f, a1 = 0.f, w;
                w = w00 * uz; v = *(float2*)&eb[8 * j + 0]; a0 = fmaf(w, v.x, a0); a1 = fmaf(w, v.y, a1);
                w = w00 * tz; v = *(float2*)&eb[8 * j + 1]; a0 = fmaf(w, v.x, a0); a1 = fmaf(w, v.y, a1);
                w = w01 * uz; v = *(float2*)&eb[8 * j + 2]; a0 = fmaf(w, v.x, a0); a1 = fmaf(w, v.y, a1);
                w = w01 * tz; v = *(float2*)&eb[8 * j + 3]; a0 = fmaf(w, v.x, a0); a1 = fmaf(w, v.y, a1);
                w = w10 * uz; v = *(float2*)&eb[8 * j + 4]; a0 = fmaf(w, v.x, a0); a1 = fmaf(w, v.y, a1);
                w = w10 * tz; v = *(float2*)&eb[8 * j + 5]; a0 = fmaf(w, v.x, a0); a1 = fmaf(w, v.y, a1);
                w = w11 * uz; v = *(float2*)&eb[8 * j + 6]; a0 = fmaf(w, v.x, a0); a1 = fmaf(w, v.y, a1);
                w = w11 * tz; v = *(float2*)&eb[8 * j + 7]; a0 = fmaf(w, v.x, a0); a1 = fmaf(w, v.y, a1);
                *(float2*)(frow + 2 * l) = make_float2(a0, a1);
            }
        }
        __syncwarp();

        // ---------- density MLP ----------
        layer_relu<32, 64>(wf + WF_L1, sm + BIAS_F, Aw, lane);
        layer_l2(wf + WF_L2, sm + BIAS_F + 64, Aw, lane);

        out[p] = expf(frow[16]);

        // ---------- SH deg-4 into cols 0..15 ----------
        {
            float nrm = sqrtf(dxr * dxr + dyr * dyr + dzr * dzr);
            float x = dxr / nrm, y = dyr / nrm, z = dzr / nrm;
            x = ((x + 1.f) * 0.5f) * 2.f - 1.f;
            y = ((y + 1.f) * 0.5f) * 2.f - 1.f;
            z = ((z + 1.f) * 0.5f) * 2.f - 1.f;
            float xx = x * x, yy = y * y, zz = z * z;
            float xy = x * y, yz = y * z, xz = x * z;
            *(float4*)(frow + 0) = make_float4(
                0.28209479177387814f,
                -0.48860251190291987f * y,
                 0.48860251190291987f * z,
                -0.48860251190291987f * x);
            *(float4*)(frow + 4) = make_float4(
                 1.0925484305920792f * xy,
                -1.0925484305920792f * yz,
                 0.94617469575756f * zz - 0.31539156525252f,
                -1.0925484305920792f * xz);
            *(float4*)(frow + 8) = make_float4(
                 0.5462742152960396f * (xx - yy),
                 0.5900435899266435f * y * (-3.0f * xx + yy),
                 2.890611442640554f * xy * z,
                 0.4570457994644657f * y * (1.0f - 5.0f * zz));
            *(float4*)(frow + 12) = make_float4(
                 0.3731763325901154f * z * (5.0f * zz - 3.0f),
                 0.4570457994644657f * x * (1.0f - 5.0f * zz),
                 1.445305721320277f * z * (xx - yy),
                 0.5900435899266435f * x * (xx - 3.0f * yy));
        }
        __syncwarp();

        // ---------- color MLP ----------
        layer_relu<32, 64>(wf + WF_C1, sm + BIAS_F + 80,  Aw, lane);
        layer_relu<64, 64>(wf + WF_C2, sm + BIAS_F + 144, Aw, lane);
        layer_relu<64, 64>(wf + WF_C3, sm + BIAS_F + 208, Aw, lane);
        layer_c4(wf + WF_C4, sm + BIAS_F + 272, Aw, lane, out, wt * 32);
    }
}

extern "C" void kernel_launch(void* const* d_in, const int* in_sizes, int n_in,
                              void* d_out, int out_size)
{
    const float* coords = (const float*)d_in[0];
    const float* dirs   = (const float*)d_in[1];
    const u64*   emb    = (const u64*)d_in[2];
    const float* dw1 = (const float*)d_in[3];
    const float* db1 = (const float*)d_in[4];
    const float* dw2 = (const float*)d_in[5];
    const float* db2 = (const float*)d_in[6];
    const float* cw1 = (const float*)d_in[7];
    const float* cb1 = (const float*)d_in[8];
    const float* cw2 = (const float*)d_in[9];
    const float* cb2 = (const float*)d_in[10];
    const float* cw3 = (const float*)d_in[11];
    const float* cb3 = (const float*)d_in[12];
    const float* cw4 = (const float*)d_in[13];
    const float* cb4 = (const float*)d_in[14];
    float* out = (float*)d_out;

    cudaFuncSetAttribute(nerf_mma_kernel,
                         cudaFuncAttributeMaxDynamicSharedMemorySize, SMEM_BYTES);

    nerf_mma_kernel<<<NCTA, THREADS, SMEM_BYTES>>>(
        coords, dirs, emb,
        dw1, db1, dw2, db2,
        cw1, cb1, cw2, cb2, cw3, cb3, cw4, cb4,
        out);
}